// round 12
// baseline (speedup 1.0000x reference)
#include <cuda_runtime.h>

#define BB     32
#define NATOM  256
#define NN     100
#define NF     42
#define NH1    50
#define NH2    50
#define ROWLEN (NN * NF * 3)          // 12600 floats per (b,n)
#define NGRP   (NN * NF / 4)          // 1050 groups of 12 floats (= 3 float4 = 4 entries)

// dE (grad of sum Ei wrt image), [B, NATOM, NF]. Device global => no allocation.
__device__ float g_dE[BB * NATOM * NF];
// 1 if neighbor buffer is int32, 0 if int64. Written by mlp_kernel block 0.
__device__ int   g_nbr_is32;

__device__ __forceinline__ float safe_tanh(float x) {
    // tanh(x) = 1 - 2/(exp(2x)+1); exact saturation at +/-inf, ~1e-6 accurate.
    float e = __expf(2.0f * x);
    return 1.0f - 2.0f / (e + 1.0f);
}

// ---------------------------------------------------------------------------
// Kernel 1: warp-per-atom MLP forward + input-gradient backward.
// Each lane owns TWO outputs (j=lane, j=lane+32) => two independent FFMA
// chains per lane (2x ILP on the 4-cyc RAW latency). Reg cap via
// __launch_bounds__(256,6) => ~42 regs => 6 CTAs/SM instead of 3.
// Block 0 also detects the neighbor dtype: values in [0,256], so for
// little-endian int64 every odd 32-bit word is 0; for int32 essentially never.
// ---------------------------------------------------------------------------
__global__ void __launch_bounds__(256, 6) mlp_kernel(
    const float* __restrict__ image,
    const unsigned int* __restrict__ nbr_words,
    const float* __restrict__ W0a, const float* __restrict__ b0a,
    const float* __restrict__ W1a, const float* __restrict__ b1a,
    const float* __restrict__ W2a, const float* __restrict__ b2a,
    const float* __restrict__ W0b, const float* __restrict__ b0b,
    const float* __restrict__ W1b, const float* __restrict__ b1b,
    const float* __restrict__ W2b, const float* __restrict__ b2b,
    float* __restrict__ Ei)
{
    __shared__ float sW0[NF * NH1];
    __shared__ float sW1[NH1 * NH2];
    __shared__ float sW2[NH2];
    __shared__ float sb0[NH1];
    __shared__ float sb1[NH2];
    __shared__ float scratch[8][NF + NH1 + NH2];
    __shared__ int s_any;

    const int tid  = threadIdx.x;
    const int warp = tid >> 5;
    const int lane = tid & 31;
    const int abase = blockIdx.x * 8;           // global atom base
    const int type  = ((abase % NATOM) >= 128) ? 1 : 0;

    const float* W0 = type ? W0b : W0a;
    const float* b0 = type ? b0b : b0a;
    const float* W1 = type ? W1b : W1a;
    const float* b1 = type ? b1b : b1a;
    const float* W2 = type ? W2b : W2a;
    const float  b2v = type ? b2b[0] : b2a[0];

    // neighbor-dtype detection (block 0 only), overlapped with weight loads
    int any = 0;
    if (blockIdx.x == 0) {
        if (tid == 0) s_any = 0;
        for (int i = tid; i < 4096; i += 256)
            if (nbr_words[2 * i + 1] != 0u) any = 1;
    }

    for (int i = tid; i < NF * NH1; i += 256)  sW0[i] = W0[i];
    for (int i = tid; i < NH1 * NH2; i += 256) sW1[i] = W1[i];
    if (tid < NH2) sW2[tid] = W2[tid];
    if (tid < NH1) sb0[tid] = b0[tid];
    if (tid < NH2) sb1[tid] = b1[tid];
    __syncthreads();

    if (blockIdx.x == 0) {
        if (any) atomicOr(&s_any, 1);
        __syncthreads();
        if (tid == 0) g_nbr_is32 = s_any;
    }

    const int a = abase + warp;                 // global atom 0..8191
    float* sx  = scratch[warp];
    float* sh0 = sx + NF;
    float* sh1 = sh0 + NH1;

    const int j1 = lane;                        // first output index
    const int j2 = lane + 32;                   // second output (valid if < 50)
    const bool has2h = (j2 < NH1);              // lanes 0..17

    // load x
    for (int f = lane; f < NF; f += 32) sx[f] = image[(size_t)a * NF + f];
    __syncwarp();

    // h0 = tanh(x W0 + b0): two independent chains per lane
    {
        float s1 = sb0[j1];
        float s2 = has2h ? sb0[j2] : 0.0f;
        #pragma unroll
        for (int f = 0; f < NF; f++) {
            const float xv = sx[f];
            s1 += xv * sW0[f * NH1 + j1];
            if (has2h) s2 += xv * sW0[f * NH1 + j2];
        }
        sh0[j1] = safe_tanh(s1);
        if (has2h) sh0[j2] = safe_tanh(s2);
    }
    __syncwarp();

    // h1 = tanh(h0 W1 + b1)
    {
        float s1 = sb1[j1];
        float s2 = has2h ? sb1[j2] : 0.0f;
        #pragma unroll
        for (int i = 0; i < NH1; i++) {
            const float hv = sh0[i];
            s1 += hv * sW1[i * NH2 + j1];
            if (has2h) s2 += hv * sW1[i * NH2 + j2];
        }
        sh1[j1] = safe_tanh(s1);
        if (has2h) sh1[j2] = safe_tanh(s2);
    }
    __syncwarp();

    // y = h1 . W2 + b2   (warp reduction)
    {
        float t = sh1[j1] * sW2[j1];
        if (has2h) t += sh1[j2] * sW2[j2];
        #pragma unroll
        for (int o = 16; o > 0; o >>= 1) t += __shfl_down_sync(0xffffffffu, t, o);
        if (lane == 0) Ei[a] = t + b2v;
    }
    __syncwarp();

    // backward: g1 = W2 * (1 - h1^2), overwrite sh1
    {
        const float h1v = sh1[j1];
        sh1[j1] = sW2[j1] * (1.0f - h1v * h1v);
        if (has2h) {
            const float h2v = sh1[j2];
            sh1[j2] = sW2[j2] * (1.0f - h2v * h2v);
        }
    }
    __syncwarp();

    // g0 = (W1 g1) * (1 - h0^2), overwrite sh0
    {
        float s1 = 0.0f, s2 = 0.0f;
        #pragma unroll
        for (int j = 0; j < NH2; j++) {
            const float gv = sh1[j];
            s1 += sW1[j1 * NH2 + j] * gv;          // row j1 of W1
            if (has2h) s2 += sW1[j2 * NH2 + j] * gv;
        }
        const float h1v = sh0[j1];
        const float r1 = s1 * (1.0f - h1v * h1v);
        float r2 = 0.0f;
        if (has2h) {
            const float h2v = sh0[j2];
            r2 = s2 * (1.0f - h2v * h2v);
        }
        __syncwarp();           // all reads of sh0 done before overwrite
        sh0[j1] = r1;
        if (has2h) sh0[j2] = r2;
    }
    __syncwarp();

    // dx = W0 g0: two output features per lane (f=lane, f=lane+32<42)
    {
        const int f2 = lane + 32;
        const bool has2f = (f2 < NF);              // lanes 0..9
        float s1 = 0.0f, s2 = 0.0f;
        #pragma unroll
        for (int i = 0; i < NH1; i++) {
            const float gv = sh0[i];
            s1 += sW0[lane * NH1 + i] * gv;        // row `lane` of W0
            if (has2f) s2 += sW0[f2 * NH1 + i] * gv;
        }
        g_dE[(size_t)a * NF + lane] = s1;
        if (has2f) g_dE[(size_t)a * NF + f2] = s2;
    }
}

// ---------------------------------------------------------------------------
// Kernel 2: deterministic Etot = sum_n Ei[b, n]
// ---------------------------------------------------------------------------
__global__ void __launch_bounds__(256) etot_kernel(
    const float* __restrict__ Ei, float* __restrict__ Etot)
{
    __shared__ float s[256];
    const int b = blockIdx.x;
    s[threadIdx.x] = Ei[b * NATOM + threadIdx.x];
    __syncthreads();
    #pragma unroll
    for (int o = 128; o > 0; o >>= 1) {
        if (threadIdx.x < o) s[threadIdx.x] += s[threadIdx.x + o];
        __syncthreads();
    }
    if (threadIdx.x == 0) Etot[b] = s[0];
}

// ---------------------------------------------------------------------------
// Kernel 3: Force[b,n,d] = sum_{k,f} dE_pad[b, nbr[b,n,k], f] * dfeat[b,n,k,f,d]
// One block per (b,n). Group-of-12 FFMA structure (R8) + two latency tweaks:
//   (a) first group's 3 LDG.128 issued BEFORE the dE gather (DRAM busy in
//       the prologue), (b) 1-stage software pipeline (6 float4 in flight,
//       ~45 regs -> still 8 CTAs/SM, warp-limited; NOT the R9 reg blowup).
// ---------------------------------------------------------------------------
__global__ void __launch_bounds__(256) force_kernel(
    const float* __restrict__ dfeat,
    const void* __restrict__ neighbor,
    float* __restrict__ force)
{
    __shared__ __align__(16) float sdE[NN * NF];   // 4200 floats = 16.8 KB
    __shared__ int   snbr[NN];
    __shared__ float sred[3][8];

    const int tid = threadIdx.x;
    const int bn  = blockIdx.x;          // b*NATOM + n
    const int b   = bn >> 8;

    if (tid < NN) {
        int j;
        if (g_nbr_is32) j = ((const int*)neighbor)[(size_t)bn * NN + tid];
        else            j = (int)((const long long*)neighbor)[(size_t)bn * NN + tid];
        snbr[tid] = j;
    }

    // Early-issue: first group's dfeat loads go out before the gather phase.
    const float4* __restrict__ df4 =
        (const float4*)(dfeat + (size_t)bn * ROWLEN);
    int g = tid;                         // 256 <= NGRP, always valid
    float4 v0 = df4[3 * g + 0];
    float4 v1 = df4[3 * g + 1];
    float4 v2 = df4[3 * g + 2];

    __syncthreads();                     // snbr ready

    // Gather dE rows for the 100 neighbors (0 => padded zero row, j => atom j-1).
    // float2-vectorized: rows are 42 floats, pairs never straddle a row.
    {
        const float* dEb = g_dE + (size_t)b * NATOM * NF;
        float2* sdE2 = (float2*)sdE;
        for (int i2 = tid; i2 < NN * NF / 2; i2 += 256) {
            const int k  = (2 * i2) / NF;
            const int f  = 2 * i2 - k * NF;
            const int j  = snbr[k];
            float2 v;
            if (j == 0) { v.x = 0.0f; v.y = 0.0f; }
            else        { v = *(const float2*)(dEb + (j - 1) * NF + f); }
            sdE2[i2] = v;
        }
    }
    __syncthreads();

    // Main loop with 1-stage prefetch: next group's loads in flight while
    // computing the current group's 12 FFMAs.
    const float4* __restrict__ sdE4 = (const float4*)sdE;
    float a0 = 0.0f, a1 = 0.0f, a2 = 0.0f;
    while (g < NGRP) {
        const int gn = g + 256;
        float4 n0, n1, n2;
        const bool more = (gn < NGRP);
        if (more) {
            n0 = df4[3 * gn + 0];
            n1 = df4[3 * gn + 1];
            n2 = df4[3 * gn + 2];
        }
        const float4 w = sdE4[g];        // weights for entries 4g..4g+3
        a0 += w.x * v0.x;  a1 += w.x * v0.y;  a2 += w.x * v0.z;
        a0 += w.y * v0.w;  a1 += w.y * v1.x;  a2 += w.y * v1.y;
        a0 += w.z * v1.z;  a1 += w.z * v1.w;  a2 += w.z * v2.x;
        a0 += w.w * v2.y;  a1 += w.w * v2.z;  a2 += w.w * v2.w;
        v0 = n0; v1 = n1; v2 = n2;
        g = gn;
    }

    #pragma unroll
    for (int o = 16; o > 0; o >>= 1) {
        a0 += __shfl_down_sync(0xffffffffu, a0, o);
        a1 += __shfl_down_sync(0xffffffffu, a1, o);
        a2 += __shfl_down_sync(0xffffffffu, a2, o);
    }
    const int warp = tid >> 5;
    if ((tid & 31) == 0) { sred[0][warp] = a0; sred[1][warp] = a1; sred[2][warp] = a2; }
    __syncthreads();

    if (tid < 3) {
        float s = 0.0f;
        #pragma unroll
        for (int w = 0; w < 8; w++) s += sred[tid][w];
        force[(size_t)bn * 3 + tid] = s;
    }
}

// ---------------------------------------------------------------------------
extern "C" void kernel_launch(void* const* d_in, const int* in_sizes, int n_in,
                              void* d_out, int out_size)
{
    const float* image    = (const float*)d_in[0];
    const float* dfeat    = (const float*)d_in[1];
    const void*  neighbor = d_in[2];
    const float* W0_0 = (const float*)d_in[3];
    const float* b0_0 = (const float*)d_in[4];
    const float* W1_0 = (const float*)d_in[5];
    const float* b1_0 = (const float*)d_in[6];
    const float* W2_0 = (const float*)d_in[7];
    const float* b2_0 = (const float*)d_in[8];
    const float* W0_1 = (const float*)d_in[9];
    const float* b0_1 = (const float*)d_in[10];
    const float* W1_1 = (const float*)d_in[11];
    const float* b1_1 = (const float*)d_in[12];
    const float* W2_1 = (const float*)d_in[13];
    const float* b2_1 = (const float*)d_in[14];

    float* out   = (float*)d_out;
    float* Etot  = out;                       // [32]
    float* Ei    = out + BB;                  // [32*256]
    float* Force = out + BB + BB * NATOM;     // [32*256*3]

    mlp_kernel<<<BB * NATOM / 8, 256>>>(
        image, (const unsigned int*)neighbor,
        W0_0, b0_0, W1_0, b1_0, W2_0, b2_0,
        W0_1, b0_1, W1_1, b1_1, W2_1, b2_1,
        Ei);
    etot_kernel<<<BB, 256>>>(Ei, Etot);
    force_kernel<<<BB * NATOM, 256>>>(dfeat, neighbor, Force);
}

// round 13
// speedup vs baseline: 1.1409x; 1.1409x over previous
#include <cuda_runtime.h>

#define BB     32
#define NATOM  256
#define NN     100
#define NF     42
#define NH1    50
#define NH2    50
#define ROWLEN (NN * NF * 3)          // 12600 floats per (b,n)
#define NGRP   (NN * NF / 4)          // 1050 groups of 12 floats (= 3 float4 = 4 entries)

// dE (grad of sum Ei wrt image), [B, NATOM, NF]. Device global => no allocation.
__device__ float g_dE[BB * NATOM * NF];
// 1 if neighbor buffer is int32, 0 if int64. Written by mlp_kernel block 0.
__device__ int   g_nbr_is32;

__device__ __forceinline__ float tanh_fast(float x) {
    // HW MUFU.TANH (sm_75+): 1 MUFU op, ~16 cyc; abs err ~5e-4 — well inside
    // the 1e-3 gate after compounding (was __expf + rcp, ~40+ cyc on the
    // critical path before every __syncwarp).
    float y;
    asm("tanh.approx.f32 %0, %1;" : "=f"(y) : "f"(x));
    return y;
}

// ---------------------------------------------------------------------------
// Kernel 1: warp-per-atom MLP forward + input-gradient backward.
// Each lane owns TWO outputs (j=lane, j=lane+32): two independent FFMA chains.
// Also: folds Etot accumulation (atomicAdd, Etot pre-zeroed by memsetAsync)
// and neighbor-dtype detection (block 0: int64 values in [0,256] have all
// odd 32-bit words zero; int32 essentially never).
// ---------------------------------------------------------------------------
__global__ void __launch_bounds__(256, 6) mlp_kernel(
    const float* __restrict__ image,
    const unsigned int* __restrict__ nbr_words,
    const float* __restrict__ W0a, const float* __restrict__ b0a,
    const float* __restrict__ W1a, const float* __restrict__ b1a,
    const float* __restrict__ W2a, const float* __restrict__ b2a,
    const float* __restrict__ W0b, const float* __restrict__ b0b,
    const float* __restrict__ W1b, const float* __restrict__ b1b,
    const float* __restrict__ W2b, const float* __restrict__ b2b,
    float* __restrict__ Ei, float* __restrict__ Etot)
{
    __shared__ float sW0[NF * NH1];
    __shared__ float sW1[NH1 * NH2];
    __shared__ float sW2[NH2];
    __shared__ float sb0[NH1];
    __shared__ float sb1[NH2];
    __shared__ float scratch[8][NF + NH1 + NH2];
    __shared__ int s_any;

    const int tid  = threadIdx.x;
    const int warp = tid >> 5;
    const int lane = tid & 31;
    const int abase = blockIdx.x * 8;           // global atom base
    const int type  = ((abase % NATOM) >= 128) ? 1 : 0;

    const float* W0 = type ? W0b : W0a;
    const float* b0 = type ? b0b : b0a;
    const float* W1 = type ? W1b : W1a;
    const float* b1 = type ? b1b : b1a;
    const float* W2 = type ? W2b : W2a;
    const float  b2v = type ? b2b[0] : b2a[0];

    // neighbor-dtype detection (block 0 only), overlapped with weight loads
    int any = 0;
    if (blockIdx.x == 0) {
        if (tid == 0) s_any = 0;
        for (int i = tid; i < 4096; i += 256)
            if (nbr_words[2 * i + 1] != 0u) any = 1;
    }

    for (int i = tid; i < NF * NH1; i += 256)  sW0[i] = W0[i];
    for (int i = tid; i < NH1 * NH2; i += 256) sW1[i] = W1[i];
    if (tid < NH2) sW2[tid] = W2[tid];
    if (tid < NH1) sb0[tid] = b0[tid];
    if (tid < NH2) sb1[tid] = b1[tid];
    __syncthreads();

    if (blockIdx.x == 0) {
        if (any) atomicOr(&s_any, 1);
        __syncthreads();
        if (tid == 0) g_nbr_is32 = s_any;
    }

    const int a = abase + warp;                 // global atom 0..8191
    float* sx  = scratch[warp];
    float* sh0 = sx + NF;
    float* sh1 = sh0 + NH1;

    const int j1 = lane;                        // first output index
    const int j2 = lane + 32;                   // second output (valid if < 50)
    const bool has2h = (j2 < NH1);              // lanes 0..17

    // load x
    for (int f = lane; f < NF; f += 32) sx[f] = image[(size_t)a * NF + f];
    __syncwarp();

    // h0 = tanh(x W0 + b0): two independent chains per lane
    {
        float s1 = sb0[j1];
        float s2 = has2h ? sb0[j2] : 0.0f;
        #pragma unroll
        for (int f = 0; f < NF; f++) {
            const float xv = sx[f];
            s1 += xv * sW0[f * NH1 + j1];
            if (has2h) s2 += xv * sW0[f * NH1 + j2];
        }
        sh0[j1] = tanh_fast(s1);
        if (has2h) sh0[j2] = tanh_fast(s2);
    }
    __syncwarp();

    // h1 = tanh(h0 W1 + b1)
    {
        float s1 = sb1[j1];
        float s2 = has2h ? sb1[j2] : 0.0f;
        #pragma unroll
        for (int i = 0; i < NH1; i++) {
            const float hv = sh0[i];
            s1 += hv * sW1[i * NH2 + j1];
            if (has2h) s2 += hv * sW1[i * NH2 + j2];
        }
        sh1[j1] = tanh_fast(s1);
        if (has2h) sh1[j2] = tanh_fast(s2);
    }
    __syncwarp();

    // y = h1 . W2 + b2   (warp reduction); Ei store + Etot atomic fold
    {
        float t = sh1[j1] * sW2[j1];
        if (has2h) t += sh1[j2] * sW2[j2];
        #pragma unroll
        for (int o = 16; o > 0; o >>= 1) t += __shfl_down_sync(0xffffffffu, t, o);
        if (lane == 0) {
            const float e = t + b2v;
            Ei[a] = e;
            atomicAdd(&Etot[a >> 8], e);
        }
    }
    __syncwarp();

    // backward: g1 = W2 * (1 - h1^2), overwrite sh1
    {
        const float h1v = sh1[j1];
        sh1[j1] = sW2[j1] * (1.0f - h1v * h1v);
        if (has2h) {
            const float h2v = sh1[j2];
            sh1[j2] = sW2[j2] * (1.0f - h2v * h2v);
        }
    }
    __syncwarp();

    // g0 = (W1 g1) * (1 - h0^2), overwrite sh0
    {
        float s1 = 0.0f, s2 = 0.0f;
        #pragma unroll
        for (int j = 0; j < NH2; j++) {
            const float gv = sh1[j];
            s1 += sW1[j1 * NH2 + j] * gv;          // row j1 of W1
            if (has2h) s2 += sW1[j2 * NH2 + j] * gv;
        }
        const float h1v = sh0[j1];
        const float r1 = s1 * (1.0f - h1v * h1v);
        float r2 = 0.0f;
        if (has2h) {
            const float h2v = sh0[j2];
            r2 = s2 * (1.0f - h2v * h2v);
        }
        __syncwarp();           // all reads of sh0 done before overwrite
        sh0[j1] = r1;
        if (has2h) sh0[j2] = r2;
    }
    __syncwarp();

    // dx = W0 g0: two output features per lane (f=lane, f=lane+32<42)
    {
        const int f2 = lane + 32;
        const bool has2f = (f2 < NF);              // lanes 0..9
        float s1 = 0.0f, s2 = 0.0f;
        #pragma unroll
        for (int i = 0; i < NH1; i++) {
            const float gv = sh0[i];
            s1 += sW0[lane * NH1 + i] * gv;        // row `lane` of W0
            if (has2f) s2 += sW0[f2 * NH1 + i] * gv;
        }
        g_dE[(size_t)a * NF + lane] = s1;
        if (has2f) g_dE[(size_t)a * NF + f2] = s2;
    }
}

// ---------------------------------------------------------------------------
// Kernel 3: Force[b,n,d] = sum_{k,f} dE_pad[b, nbr[b,n,k], f] * dfeat[b,n,k,f,d]
// EXACT R8 structure (regs ~30, 8 CTAs/SM — proven optimum; prefetch regs
// regressed twice). Group-of-12: 1 LDS.128 + 3 LDG.128 (__ldcs, streaming)
// + 12 plain FFMAs per group, zero div/mod.
// ---------------------------------------------------------------------------
__global__ void __launch_bounds__(256) force_kernel(
    const float* __restrict__ dfeat,
    const void* __restrict__ neighbor,
    float* __restrict__ force)
{
    __shared__ __align__(16) float sdE[NN * NF];   // 4200 floats = 16.8 KB
    __shared__ int   snbr[NN];
    __shared__ float sred[3][8];

    const int tid = threadIdx.x;
    const int bn  = blockIdx.x;          // b*NATOM + n
    const int b   = bn >> 8;

    if (tid < NN) {
        int j;
        if (g_nbr_is32) j = ((const int*)neighbor)[(size_t)bn * NN + tid];
        else            j = (int)((const long long*)neighbor)[(size_t)bn * NN + tid];
        snbr[tid] = j;
    }
    __syncthreads();

    // Gather dE rows for the 100 neighbors (0 => padded zero row, j => atom j-1).
    // float2-vectorized: rows are 42 floats, pairs never straddle a row.
    {
        const float* dEb = g_dE + (size_t)b * NATOM * NF;
        float2* sdE2 = (float2*)sdE;
        for (int i2 = tid; i2 < NN * NF / 2; i2 += 256) {
            const int k  = (2 * i2) / NF;
            const int f  = 2 * i2 - k * NF;
            const int j  = snbr[k];
            float2 v;
            if (j == 0) { v.x = 0.0f; v.y = 0.0f; }
            else        { v = *(const float2*)(dEb + (j - 1) * NF + f); }
            sdE2[i2] = v;
        }
    }
    __syncthreads();

    // Stream dfeat row: thread handles group g (= floats [12g, 12g+12)).
    const float4* __restrict__ df4 =
        (const float4*)(dfeat + (size_t)bn * ROWLEN);
    const float4* __restrict__ sdE4 = (const float4*)sdE;

    float a0 = 0.0f, a1 = 0.0f, a2 = 0.0f;
    for (int g = tid; g < NGRP; g += 256) {
        const float4 w  = sdE4[g];           // weights for entries 4g..4g+3
        const float4 v0 = __ldcs(&df4[3 * g + 0]);
        const float4 v1 = __ldcs(&df4[3 * g + 1]);
        const float4 v2 = __ldcs(&df4[3 * g + 2]);
        // entry 4g
        a0 += w.x * v0.x;  a1 += w.x * v0.y;  a2 += w.x * v0.z;
        // entry 4g+1
        a0 += w.y * v0.w;  a1 += w.y * v1.x;  a2 += w.y * v1.y;
        // entry 4g+2
        a0 += w.z * v1.z;  a1 += w.z * v1.w;  a2 += w.z * v2.x;
        // entry 4g+3
        a0 += w.w * v2.y;  a1 += w.w * v2.z;  a2 += w.w * v2.w;
    }

    #pragma unroll
    for (int o = 16; o > 0; o >>= 1) {
        a0 += __shfl_down_sync(0xffffffffu, a0, o);
        a1 += __shfl_down_sync(0xffffffffu, a1, o);
        a2 += __shfl_down_sync(0xffffffffu, a2, o);
    }
    const int warp = tid >> 5;
    if ((tid & 31) == 0) { sred[0][warp] = a0; sred[1][warp] = a1; sred[2][warp] = a2; }
    __syncthreads();

    if (tid < 3) {
        float s = 0.0f;
        #pragma unroll
        for (int w = 0; w < 8; w++) s += sred[tid][w];
        force[(size_t)bn * 3 + tid] = s;
    }
}

// ---------------------------------------------------------------------------
extern "C" void kernel_launch(void* const* d_in, const int* in_sizes, int n_in,
                              void* d_out, int out_size)
{
    const float* image    = (const float*)d_in[0];
    const float* dfeat    = (const float*)d_in[1];
    const void*  neighbor = d_in[2];
    const float* W0_0 = (const float*)d_in[3];
    const float* b0_0 = (const float*)d_in[4];
    const float* W1_0 = (const float*)d_in[5];
    const float* b1_0 = (const float*)d_in[6];
    const float* W2_0 = (const float*)d_in[7];
    const float* b2_0 = (const float*)d_in[8];
    const float* W0_1 = (const float*)d_in[9];
    const float* b0_1 = (const float*)d_in[10];
    const float* W1_1 = (const float*)d_in[11];
    const float* b1_1 = (const float*)d_in[12];
    const float* W2_1 = (const float*)d_in[13];
    const float* b2_1 = (const float*)d_in[14];

    float* out   = (float*)d_out;
    float* Etot  = out;                       // [32]
    float* Ei    = out + BB;                  // [32*256]
    float* Force = out + BB + BB * NATOM;     // [32*256*3]

    // Zero Etot (output poisoned to 0xAA before timing); capturable async memset.
    cudaMemsetAsync(Etot, 0, BB * sizeof(float));

    mlp_kernel<<<BB * NATOM / 8, 256>>>(
        image, (const unsigned int*)neighbor,
        W0_0, b0_0, W1_0, b1_0, W2_0, b2_0,
        W0_1, b0_1, W1_1, b1_1, W2_1, b2_1,
        Ei, Etot);
    force_kernel<<<BB * NATOM, 256>>>(dfeat, neighbor, Force);
}

// round 14
// speedup vs baseline: 1.2474x; 1.0933x over previous
#include <cuda_runtime.h>

#define BB     32
#define NATOM  256
#define NN     100
#define NF     42
#define NH1    50
#define NH2    50
#define APW    4                      // atoms per warp (weight-LDS amortization)
#define ROWLEN (NN * NF * 3)          // 12600 floats per (b,n)
#define NGRP   (NN * NF / 4)          // 1050 groups of 12 floats (= 3 float4 = 4 entries)

// dE (grad of sum Ei wrt image), [B, NATOM, NF]. Device global => no allocation.
__device__ float g_dE[BB * NATOM * NF];
// 1 if neighbor buffer is int32, 0 if int64. Written by mlp_kernel block 0.
__device__ int   g_nbr_is32;

__device__ __forceinline__ float tanh_fast(float x) {
    float y;
    asm("tanh.approx.f32 %0, %1;" : "=f"(y) : "f"(x));
    return y;
}

// ---------------------------------------------------------------------------
// Kernel 1: MLP fwd + input-grad bwd, 4 atoms per warp.
// mlp is LDS-crossbar-bound (1 warp-LDS/cyc/SM): each weight LDS now feeds
// 4 atoms (8 FFMAs) instead of 1 atom (2 FFMAs) -> LDS/MAC 1.5 -> 0.75.
// Block = 256 thr = 8 warps = 32 atoms (type-uniform: 32 | 128). Grid = 256.
// Block 0 also detects neighbor dtype (int64 values in [0,256] => all odd
// 32-bit words zero; int32 essentially never).
// ---------------------------------------------------------------------------
__global__ void __launch_bounds__(256) mlp_kernel(
    const float* __restrict__ image,
    const unsigned int* __restrict__ nbr_words,
    const float* __restrict__ W0a, const float* __restrict__ b0a,
    const float* __restrict__ W1a, const float* __restrict__ b1a,
    const float* __restrict__ W2a, const float* __restrict__ b2a,
    const float* __restrict__ W0b, const float* __restrict__ b0b,
    const float* __restrict__ W1b, const float* __restrict__ b1b,
    const float* __restrict__ W2b, const float* __restrict__ b2b,
    float* __restrict__ Ei, float* __restrict__ Etot)
{
    __shared__ float sW0[NF * NH1];
    __shared__ float sW1[NH1 * NH2];
    __shared__ float sW2[NH2];
    __shared__ float sb0[NH1];
    __shared__ float sb1[NH2];
    __shared__ float sxw[8][APW * NF];    // per-warp x rows (contiguous 168)
    __shared__ float sh0s[8][APW * NH1];
    __shared__ float sh1s[8][APW * NH2];
    __shared__ int s_any;

    const int tid  = threadIdx.x;
    const int warp = tid >> 5;
    const int lane = tid & 31;
    const int abase = blockIdx.x * 32 + warp * APW;   // 4 consecutive atoms
    const int type  = ((abase % NATOM) >= 128) ? 1 : 0;

    const float* W0 = type ? W0b : W0a;
    const float* b0 = type ? b0b : b0a;
    const float* W1 = type ? W1b : W1a;
    const float* b1 = type ? b1b : b1a;
    const float* W2 = type ? W2b : W2a;
    const float  b2v = type ? b2b[0] : b2a[0];

    // neighbor-dtype detection (block 0 only), overlapped with weight loads
    int any = 0;
    if (blockIdx.x == 0) {
        if (tid == 0) s_any = 0;
        for (int i = tid; i < 4096; i += 256)
            if (nbr_words[2 * i + 1] != 0u) any = 1;
    }

    for (int i = tid; i < NF * NH1; i += 256)  sW0[i] = W0[i];
    for (int i = tid; i < NH1 * NH2; i += 256) sW1[i] = W1[i];
    if (tid < NH2) sW2[tid] = W2[tid];
    if (tid < NH1) sb0[tid] = b0[tid];
    if (tid < NH2) sb1[tid] = b1[tid];
    __syncthreads();

    if (blockIdx.x == 0) {
        if (any) atomicOr(&s_any, 1);
        __syncthreads();
        if (tid == 0) g_nbr_is32 = s_any;
    }

    float* sx  = sxw[warp];
    float* sh0 = sh0s[warp];
    float* sh1 = sh1s[warp];

    const int j1 = lane;
    const int j2 = lane + 32;
    const bool has2h = (j2 < NH1);             // lanes 0..17

    // load 4 atoms' x rows (contiguous 4*42 floats in gmem)
    for (int i = lane; i < APW * NF; i += 32)
        sx[i] = image[(size_t)abase * NF + i];
    __syncwarp();

    // h0 = tanh(x W0 + b0): 2 outputs x 4 atoms = 8 chains per lane
    {
        float s1[APW], s2[APW];
        #pragma unroll
        for (int t = 0; t < APW; t++) { s1[t] = sb0[j1]; s2[t] = has2h ? sb0[j2] : 0.0f; }
        #pragma unroll
        for (int f = 0; f < NF; f++) {
            const float w1 = sW0[f * NH1 + j1];
            const float w2 = has2h ? sW0[f * NH1 + j2] : 0.0f;
            #pragma unroll
            for (int t = 0; t < APW; t++) {
                const float xv = sx[t * NF + f];
                s1[t] += xv * w1;
                s2[t] += xv * w2;
            }
        }
        #pragma unroll
        for (int t = 0; t < APW; t++) {
            sh0[t * NH1 + j1] = tanh_fast(s1[t]);
            if (has2h) sh0[t * NH1 + j2] = tanh_fast(s2[t]);
        }
    }
    __syncwarp();

    // h1 = tanh(h0 W1 + b1)
    {
        float s1[APW], s2[APW];
        #pragma unroll
        for (int t = 0; t < APW; t++) { s1[t] = sb1[j1]; s2[t] = has2h ? sb1[j2] : 0.0f; }
        #pragma unroll
        for (int i = 0; i < NH1; i++) {
            const float w1 = sW1[i * NH2 + j1];
            const float w2 = has2h ? sW1[i * NH2 + j2] : 0.0f;
            #pragma unroll
            for (int t = 0; t < APW; t++) {
                const float hv = sh0[t * NH1 + i];
                s1[t] += hv * w1;
                s2[t] += hv * w2;
            }
        }
        #pragma unroll
        for (int t = 0; t < APW; t++) {
            sh1[t * NH2 + j1] = tanh_fast(s1[t]);
            if (has2h) sh1[t * NH2 + j2] = tanh_fast(s2[t]);
        }
    }
    __syncwarp();

    // y = h1 . W2 + b2 per atom; Ei store + Etot atomic fold
    {
        const float w2a = sW2[j1];
        const float w2b = has2h ? sW2[j2] : 0.0f;
        #pragma unroll
        for (int t = 0; t < APW; t++) {
            float v = sh1[t * NH2 + j1] * w2a;
            if (has2h) v += sh1[t * NH2 + j2] * w2b;
            #pragma unroll
            for (int o = 16; o > 0; o >>= 1) v += __shfl_down_sync(0xffffffffu, v, o);
            if (lane == 0) {
                const float e = v + b2v;
                Ei[abase + t] = e;
                atomicAdd(&Etot[(abase + t) >> 8], e);
            }
        }
    }
    __syncwarp();

    // g1 = W2 * (1 - h1^2), overwrite sh1 (own elements only)
    {
        const float w2a = sW2[j1];
        const float w2b = has2h ? sW2[j2] : 0.0f;
        #pragma unroll
        for (int t = 0; t < APW; t++) {
            const float h1v = sh1[t * NH2 + j1];
            sh1[t * NH2 + j1] = w2a * (1.0f - h1v * h1v);
            if (has2h) {
                const float h2v = sh1[t * NH2 + j2];
                sh1[t * NH2 + j2] = w2b * (1.0f - h2v * h2v);
            }
        }
    }
    __syncwarp();

    // g0 = (W1 g1) * (1 - h0^2), overwrite sh0
    {
        float s1[APW], s2[APW];
        #pragma unroll
        for (int t = 0; t < APW; t++) { s1[t] = 0.0f; s2[t] = 0.0f; }
        #pragma unroll
        for (int j = 0; j < NH2; j++) {
            const float w1 = sW1[j1 * NH2 + j];                  // row j1 of W1
            const float w2 = has2h ? sW1[j2 * NH2 + j] : 0.0f;
            #pragma unroll
            for (int t = 0; t < APW; t++) {
                const float gv = sh1[t * NH2 + j];
                s1[t] += w1 * gv;
                s2[t] += w2 * gv;
            }
        }
        #pragma unroll
        for (int t = 0; t < APW; t++) {
            const float h1v = sh0[t * NH1 + j1];
            sh0[t * NH1 + j1] = s1[t] * (1.0f - h1v * h1v);      // own element
            if (has2h) {
                const float h2v = sh0[t * NH1 + j2];
                sh0[t * NH1 + j2] = s2[t] * (1.0f - h2v * h2v);
            }
        }
    }
    __syncwarp();

    // dx = W0 g0: output features f=lane, f=lane+32 (<42) per atom
    {
        const int f2 = lane + 32;
        const bool has2f = (f2 < NF);          // lanes 0..9
        float s1[APW], s2[APW];
        #pragma unroll
        for (int t = 0; t < APW; t++) { s1[t] = 0.0f; s2[t] = 0.0f; }
        #pragma unroll
        for (int i = 0; i < NH1; i++) {
            const float w1 = sW0[lane * NH1 + i];               // row `lane` of W0
            const float w2 = has2f ? sW0[f2 * NH1 + i] : 0.0f;
            #pragma unroll
            for (int t = 0; t < APW; t++) {
                const float gv = sh0[t * NH1 + i];
                s1[t] += w1 * gv;
                s2[t] += w2 * gv;
            }
        }
        #pragma unroll
        for (int t = 0; t < APW; t++) {
            g_dE[(size_t)(abase + t) * NF + lane] = s1[t];
            if (has2f) g_dE[(size_t)(abase + t) * NF + f2] = s2[t];
        }
    }
}

// ---------------------------------------------------------------------------
// Kernel 3: Force — FROZEN R13 version (30 regs = exactly 8 CTAs/SM on the
// 64K regfile; any extra register drops a CTA and regresses — proven twice).
// ---------------------------------------------------------------------------
__global__ void __launch_bounds__(256) force_kernel(
    const float* __restrict__ dfeat,
    const void* __restrict__ neighbor,
    float* __restrict__ force)
{
    __shared__ __align__(16) float sdE[NN * NF];   // 4200 floats = 16.8 KB
    __shared__ int   snbr[NN];
    __shared__ float sred[3][8];

    const int tid = threadIdx.x;
    const int bn  = blockIdx.x;          // b*NATOM + n
    const int b   = bn >> 8;

    if (tid < NN) {
        int j;
        if (g_nbr_is32) j = ((const int*)neighbor)[(size_t)bn * NN + tid];
        else            j = (int)((const long long*)neighbor)[(size_t)bn * NN + tid];
        snbr[tid] = j;
    }
    __syncthreads();

    {
        const float* dEb = g_dE + (size_t)b * NATOM * NF;
        float2* sdE2 = (float2*)sdE;
        for (int i2 = tid; i2 < NN * NF / 2; i2 += 256) {
            const int k  = (2 * i2) / NF;
            const int f  = 2 * i2 - k * NF;
            const int j  = snbr[k];
            float2 v;
            if (j == 0) { v.x = 0.0f; v.y = 0.0f; }
            else        { v = *(const float2*)(dEb + (j - 1) * NF + f); }
            sdE2[i2] = v;
        }
    }
    __syncthreads();

    const float4* __restrict__ df4 =
        (const float4*)(dfeat + (size_t)bn * ROWLEN);
    const float4* __restrict__ sdE4 = (const float4*)sdE;

    float a0 = 0.0f, a1 = 0.0f, a2 = 0.0f;
    for (int g = tid; g < NGRP; g += 256) {
        const float4 w  = sdE4[g];
        const float4 v0 = __ldcs(&df4[3 * g + 0]);
        const float4 v1 = __ldcs(&df4[3 * g + 1]);
        const float4 v2 = __ldcs(&df4[3 * g + 2]);
        a0 += w.x * v0.x;  a1 += w.x * v0.y;  a2 += w.x * v0.z;
        a0 += w.y * v0.w;  a1 += w.y * v1.x;  a2 += w.y * v1.y;
        a0 += w.z * v1.z;  a1 += w.z * v1.w;  a2 += w.z * v2.x;
        a0 += w.w * v2.y;  a1 += w.w * v2.z;  a2 += w.w * v2.w;
    }

    #pragma unroll
    for (int o = 16; o > 0; o >>= 1) {
        a0 += __shfl_down_sync(0xffffffffu, a0, o);
        a1 += __shfl_down_sync(0xffffffffu, a1, o);
        a2 += __shfl_down_sync(0xffffffffu, a2, o);
    }
    const int warp = tid >> 5;
    if ((tid & 31) == 0) { sred[0][warp] = a0; sred[1][warp] = a1; sred[2][warp] = a2; }
    __syncthreads();

    if (tid < 3) {
        float s = 0.0f;
        #pragma unroll
        for (int w = 0; w < 8; w++) s += sred[tid][w];
        force[(size_t)bn * 3 + tid] = s;
    }
}

// ---------------------------------------------------------------------------
extern "C" void kernel_launch(void* const* d_in, const int* in_sizes, int n_in,
                              void* d_out, int out_size)
{
    const float* image    = (const float*)d_in[0];
    const float* dfeat    = (const float*)d_in[1];
    const void*  neighbor = d_in[2];
    const float* W0_0 = (const float*)d_in[3];
    const float* b0_0 = (const float*)d_in[4];
    const float* W1_0 = (const float*)d_in[5];
    const float* b1_0 = (const float*)d_in[6];
    const float* W2_0 = (const float*)d_in[7];
    const float* b2_0 = (const float*)d_in[8];
    const float* W0_1 = (const float*)d_in[9];
    const float* b0_1 = (const float*)d_in[10];
    const float* W1_1 = (const float*)d_in[11];
    const float* b1_1 = (const float*)d_in[12];
    const float* W2_1 = (const float*)d_in[13];
    const float* b2_1 = (const float*)d_in[14];

    float* out   = (float*)d_out;
    float* Etot  = out;                       // [32]
    float* Ei    = out + BB;                  // [32*256]
    float* Force = out + BB + BB * NATOM;     // [32*256*3]

    cudaMemsetAsync(Etot, 0, BB * sizeof(float));

    mlp_kernel<<<BB * NATOM / 32, 256>>>(
        image, (const unsigned int*)neighbor,
        W0_0, b0_0, W1_0, b1_0, W2_0, b2_0,
        W0_1, b0_1, W1_1, b1_1, W2_1, b2_1,
        Ei, Etot);
    force_kernel<<<BB * NATOM, 256>>>(dfeat, neighbor, Force);
}